// round 4
// baseline (speedup 1.0000x reference)
#include <cuda_runtime.h>
#include <cstddef>

#define NMAT 32768
#define CDIM 128
#define NDIM 64
#define MATSZ 4096  // 64*64

// Scratch (static device arrays: the sanctioned alloc-free workaround)
__device__ float g_logX[(size_t)NMAT * MATSZ];   // 512 MB
__device__ float g_logP[CDIM * MATSZ];           // 2 MB
__device__ float g_B[MATSZ * CDIM];              // A_sym, k-major for GEMM (2 MB)
__device__ float g_q[CDIM];                      // tr(logP_c * A_sym_c)

// ---------------------------------------------------------------------------
// Build B[k][c] = A_sym_c[i][j], k = i*64+j, where A_sym = tril(A,-1)+tril^T+diag
// ---------------------------------------------------------------------------
__global__ void prep_b_kernel(const float* __restrict__ A) {
    int lin = blockIdx.x * blockDim.x + threadIdx.x;   // 0 .. 4096*128-1
    int c = lin & (CDIM - 1);
    int k = lin >> 7;
    int i = k >> 6, j = k & 63;
    float v;
    if (i == j)      v = A[(size_t)c * MATSZ + i * 64 + i];
    else if (i > j)  v = A[(size_t)c * MATSZ + i * 64 + j];
    else             v = A[(size_t)c * MATSZ + j * 64 + i];
    g_B[(size_t)k * CDIM + c] = v;
}

// ---------------------------------------------------------------------------
// Batched Jacobi eigensolver + logm. One CTA (256 threads) per 64x64 SPD matrix.
// Tournament (round-robin) ordering: 32 disjoint pivot pairs per round,
// 63 rounds per sweep. The 1024 2x2 (row-pair x col-pair) blocks exactly
// partition A, so the fused two-sided update needs no intra-phase sync.
// ---------------------------------------------------------------------------
__global__ __launch_bounds__(256) void jacobi_logm_kernel(
    const float* __restrict__ src, float* __restrict__ dst) {
    __shared__ float sA[64][65];
    __shared__ float sV[64][65];
    __shared__ float sc[32], ss[32];
    __shared__ int   sp[32], sq[32];
    __shared__ float sred[256];
    __shared__ float sl[64];
    __shared__ int   sdone;
    __shared__ float sfrob2;

    const int tid = threadIdx.x;
    const float* Xm = src + (size_t)blockIdx.x * MATSZ;

    // Load A, init V = I
    #pragma unroll
    for (int t = 0; t < 16; t++) {
        int idx = tid + t * 256;
        int r = idx >> 6, c = idx & 63;
        sA[r][c] = Xm[idx];
        sV[r][c] = (r == c) ? 1.0f : 0.0f;
    }
    __syncthreads();

    // Frobenius norm^2 (for convergence tolerance)
    {
        float acc = 0.0f;
        #pragma unroll
        for (int t = 0; t < 16; t++) {
            int idx = tid + t * 256;
            float v = sA[idx >> 6][idx & 63];
            acc += v * v;
        }
        sred[tid] = acc;
        __syncthreads();
        for (int o = 128; o > 0; o >>= 1) {
            if (tid < o) sred[tid] += sred[tid + o];
            __syncthreads();
        }
        if (tid == 0) { sfrob2 = sred[0]; sdone = 0; }
        __syncthreads();
    }
    const float tol2 = 1e-14f * sfrob2;   // off/frob < 1e-7

    for (int sweep = 0; sweep < 10; sweep++) {
        for (int r = 0; r < 63; r++) {
            // --- rotation parameters for the 32 pairs of this round ---
            if (tid < 32) {
                int p, q;
                if (tid == 0) { p = 0; q = 1 + (r % 63); }
                else {
                    p = 1 + ((tid + r) % 63);
                    q = 1 + ((63 - tid + r) % 63);
                }
                if (p > q) { int t = p; p = q; q = t; }
                float app = sA[p][p], aqq = sA[q][q], apq = sA[p][q];
                float cc, sn;
                if (fabsf(apq) < 1e-36f) { cc = 1.0f; sn = 0.0f; }
                else {
                    float tau = (aqq - app) / (2.0f * apq);
                    float t = copysignf(1.0f, tau) /
                              (fabsf(tau) + sqrtf(1.0f + tau * tau));
                    cc = rsqrtf(1.0f + t * t);
                    sn = t * cc;
                }
                sp[tid] = p; sq[tid] = q; sc[tid] = cc; ss[tid] = sn;
            }
            __syncthreads();

            // --- fused two-sided update: 4 disjoint 2x2 blocks per thread ---
            #pragma unroll
            for (int t = 0; t < 4; t++) {
                int blk = tid + t * 256;          // 0..1023
                int bi = blk >> 5, bj = blk & 31;
                int pi = sp[bi], qi = sq[bi];
                int pj = sp[bj], qj = sq[bj];
                float ci = sc[bi], si = ss[bi];
                float cj = sc[bj], sj = ss[bj];
                float a  = sA[pi][pj], b  = sA[pi][qj];
                float c2 = sA[qi][pj], d  = sA[qi][qj];
                // right (column) rotation G_j
                float a1 = cj * a  - sj * b;
                float b1 = sj * a  + cj * b;
                float c1 = cj * c2 - sj * d;
                float d1 = sj * c2 + cj * d;
                // left (row) rotation G_i^T
                sA[pi][pj] = ci * a1 - si * c1;
                sA[qi][pj] = si * a1 + ci * c1;
                sA[pi][qj] = ci * b1 - si * d1;
                sA[qi][qj] = si * b1 + ci * d1;
            }
            // --- V <- V * G : 8 disjoint element-pairs per thread ---
            #pragma unroll
            for (int t = 0; t < 8; t++) {
                int idx = tid + t * 256;          // 0..2047
                int row = idx >> 5, j = idx & 31;
                int pj = sp[j], qj = sq[j];
                float cj = sc[j], sj = ss[j];
                float x = sV[row][pj], y = sV[row][qj];
                sV[row][pj] = cj * x - sj * y;
                sV[row][qj] = sj * x + cj * y;
            }
            __syncthreads();
        }
        // --- per-sweep convergence check (off-diagonal Frobenius^2) ---
        float acc = 0.0f;
        #pragma unroll
        for (int t = 0; t < 16; t++) {
            int idx = tid + t * 256;
            int i = idx >> 6, j = idx & 63;
            if (i != j) { float v = sA[i][j]; acc += v * v; }
        }
        sred[tid] = acc;
        __syncthreads();
        for (int o = 128; o > 0; o >>= 1) {
            if (tid < o) sred[tid] += sred[tid + o];
            __syncthreads();
        }
        if (tid == 0) sdone = (sred[0] < tol2) ? 1 : 0;
        __syncthreads();
        if (sdone) break;
    }

    // log of eigenvalues
    if (tid < 64) sl[tid] = logf(fmaxf(sA[tid][tid], 1e-12f));
    __syncthreads();

    // logm = V * diag(log lambda) * V^T  -> global scratch (coalesced)
    float* out = dst + (size_t)blockIdx.x * MATSZ;
    #pragma unroll
    for (int t = 0; t < 16; t++) {
        int idx = tid + t * 256;
        int i = idx >> 6, j = idx & 63;
        float acc = 0.0f;
        #pragma unroll
        for (int k = 0; k < 64; k++)
            acc += (sV[i][k] * sl[k]) * sV[j][k];
        out[idx] = acc;
    }
}

// ---------------------------------------------------------------------------
// q[c] = tr(logP_c * A_sym_c) = sum_k logP[c][k] * B[k][c]
// ---------------------------------------------------------------------------
__global__ void compute_q_kernel() {
    int c = blockIdx.x;
    int tid = threadIdx.x;
    __shared__ float sred[256];
    float acc = 0.0f;
    for (int k = tid; k < MATSZ; k += 256)
        acc += g_logP[(size_t)c * MATSZ + k] * g_B[(size_t)k * CDIM + c];
    sred[tid] = acc;
    __syncthreads();
    for (int o = 128; o > 0; o >>= 1) {
        if (tid < o) sred[tid] += sred[tid + o];
        __syncthreads();
    }
    if (tid == 0) g_q[c] = sred[0];
}

// ---------------------------------------------------------------------------
// SGEMM: out[M x 128] = logX[M x 4096] @ B[4096 x 128] - q[c]
// BM=64, BN=128, BK=16, TM=TN=8, 128 threads.
// ---------------------------------------------------------------------------
#define BM 64
#define BN 128
#define BK 16
__global__ __launch_bounds__(128) void gemm_kernel(
    const float* __restrict__ Amat, float* __restrict__ out) {
    __shared__ float As[BK][BM];   // transposed A tile
    __shared__ float Bs[BK][BN];
    __shared__ float sqv[BN];

    int tid = threadIdx.x;
    int rowg = tid >> 4;    // 0..7
    int colg = tid & 15;    // 0..15
    size_t row0 = (size_t)blockIdx.x * BM;

    if (tid < BN) sqv[tid] = g_q[tid];

    float acc[8][8];
    #pragma unroll
    for (int i = 0; i < 8; i++)
        #pragma unroll
        for (int j = 0; j < 8; j++) acc[i][j] = 0.0f;

    for (int kt = 0; kt < MATSZ; kt += BK) {
        // load A tile 64x16 (transpose into As)
        #pragma unroll
        for (int l = 0; l < 2; l++) {
            int lin = tid + l * 128;          // 0..255, 4 floats each
            int r = lin >> 2;                 // 0..63
            int k4 = (lin & 3) * 4;           // 0,4,8,12
            float4 v = *(const float4*)(Amat + (row0 + r) * MATSZ + kt + k4);
            As[k4 + 0][r] = v.x; As[k4 + 1][r] = v.y;
            As[k4 + 2][r] = v.z; As[k4 + 3][r] = v.w;
        }
        // load B tile 16x128
        #pragma unroll
        for (int l = 0; l < 4; l++) {
            int lin = tid + l * 128;          // 0..511, 4 floats each
            int r = lin >> 5;                 // 0..15
            int c4 = (lin & 31) * 4;
            *(float4*)&Bs[r][c4] =
                *(const float4*)(g_B + (size_t)(kt + r) * CDIM + c4);
        }
        __syncthreads();
        #pragma unroll
        for (int k = 0; k < BK; k++) {
            float ra[8], rb[8];
            #pragma unroll
            for (int i = 0; i < 8; i++) ra[i] = As[k][rowg * 8 + i];
            #pragma unroll
            for (int j = 0; j < 8; j++) rb[j] = Bs[k][colg * 8 + j];
            #pragma unroll
            for (int i = 0; i < 8; i++)
                #pragma unroll
                for (int j = 0; j < 8; j++)
                    acc[i][j] += ra[i] * rb[j];
        }
        __syncthreads();
    }
    #pragma unroll
    for (int i = 0; i < 8; i++) {
        size_t rr = row0 + rowg * 8 + i;
        #pragma unroll
        for (int j = 0; j < 8; j++) {
            int cc = colg * 8 + j;
            out[rr * CDIM + cc] = acc[i][j] - sqv[cc];
        }
    }
}

// ---------------------------------------------------------------------------
extern "C" void kernel_launch(void* const* d_in, const int* in_sizes, int n_in,
                              void* d_out, int out_size) {
    const float* X = (const float*)d_in[0];   // (32768, 64, 64)
    const float* P = (const float*)d_in[1];   // (128, 64, 64)
    const float* A = (const float*)d_in[2];   // (128, 64, 64)
    float* out = (float*)d_out;               // (32768, 128)

    float *p_logX, *p_logP;
    cudaGetSymbolAddress((void**)&p_logX, g_logX);
    cudaGetSymbolAddress((void**)&p_logP, g_logP);

    // A_sym in k-major layout
    prep_b_kernel<<<(MATSZ * CDIM) / 256, 256>>>(A);
    // logm of prototypes, then q[c] = tr(logP_c A_sym_c)
    jacobi_logm_kernel<<<CDIM, 256>>>(P, p_logP);
    compute_q_kernel<<<CDIM, 256>>>();
    // logm of all inputs
    jacobi_logm_kernel<<<NMAT, 256>>>(X, p_logX);
    // logits = logX @ B - q
    gemm_kernel<<<NMAT / BM, 128>>>(p_logX, out);
}

// round 6
// speedup vs baseline: 1.6159x; 1.6159x over previous
#include <cuda_runtime.h>
#include <cstddef>

#define NMAT 32768
#define CDIM 128
#define NDIM 64
#define MATSZ 4096  // 64*64

// Scratch (static device arrays: the sanctioned alloc-free workaround)
__device__ float g_logX[(size_t)NMAT * MATSZ];   // 512 MB
__device__ float g_logP[CDIM * MATSZ];           // 2 MB
__device__ float g_B[MATSZ * CDIM];              // A_sym, k-major for GEMM (2 MB)
__device__ float g_q[CDIM];                      // tr(logP_c * A_sym_c)

// ---------------------------------------------------------------------------
// Build B[k][c] = A_sym_c[i][j], k = i*64+j, where A_sym = tril(A,-1)+tril^T+diag
// ---------------------------------------------------------------------------
__global__ void prep_b_kernel(const float* __restrict__ A) {
    int lin = blockIdx.x * blockDim.x + threadIdx.x;   // 0 .. 4096*128-1
    int c = lin & (CDIM - 1);
    int k = lin >> 7;
    int i = k >> 6, j = k & 63;
    float v;
    if (i == j)      v = A[(size_t)c * MATSZ + i * 64 + i];
    else if (i > j)  v = A[(size_t)c * MATSZ + i * 64 + j];
    else             v = A[(size_t)c * MATSZ + j * 64 + i];
    g_B[(size_t)k * CDIM + c] = v;
}

// ---------------------------------------------------------------------------
// Batched Jacobi eigensolver + logm. One CTA (256 threads) per 64x64 SPD matrix.
// Tournament ordering: 32 disjoint pivot pairs per round, 63 rounds per sweep.
// Symmetric-half A updates (only 496 bi<bj blocks, canonical upper storage),
// conflict-free V updates, Demmel-Veselic relative rotation threshold with
// per-round ballot skip mask. Converged when a full sweep applies no rotation.
// ---------------------------------------------------------------------------
__global__ __launch_bounds__(256, 3) void jacobi_logm_kernel(
    const float* __restrict__ src, float* __restrict__ dst) {
    __shared__ float sA[64][65];
    __shared__ float sV[64][65];
    __shared__ float2 scs[32];          // (c, s) per pair
    __shared__ int    spq[32];          // (p<<8)|q per pair
    __shared__ unsigned short sblk[496];// (bi<<8)|bj, bi<bj
    __shared__ float sl[64];
    __shared__ unsigned sskip;          // bit j = pair j rotated this round
    __shared__ int sAny;

    const int tid  = threadIdx.x;
    const int lane = tid & 31;
    const int w    = tid >> 5;
    const float* Xm = src + (size_t)blockIdx.x * MATSZ;

    // Build off-diagonal block-pair table (once per CTA)
    for (int l = tid; l < 496; l += 256) {
        float f = (63.0f - sqrtf((float)(3969 - 8 * l))) * 0.5f;
        int bi = (int)f;
        if (bi > 30) bi = 30;
        while ((63 * bi - bi * bi) / 2 > l) bi--;
        while ((63 * (bi + 1) - (bi + 1) * (bi + 1)) / 2 <= l) bi++;
        int off = (63 * bi - bi * bi) / 2;
        int bj = bi + 1 + (l - off);
        sblk[l] = (unsigned short)((bi << 8) | bj);
    }

    // Load A, init V = I
    #pragma unroll
    for (int t = 0; t < 16; t++) {
        int idx = tid + t * 256;
        int r = idx >> 6, c = idx & 63;
        sA[r][c] = Xm[idx];
        sV[r][c] = (r == c) ? 1.0f : 0.0f;
    }
    __syncthreads();

    const float eps2 = 4e-14f;   // (2e-7)^2 relative rotation threshold

    for (int sweep = 0; sweep < 12; sweep++) {
        if (tid == 0) sAny = 0;
        __syncthreads();
        for (int r = 0; r < 63; r++) {
            // --- phase 1 (warp 0): rotation params + diagonal-block update ---
            if (w == 0) {
                int p, q;
                if (lane == 0) { p = 0; q = 1 + (r % 63); }
                else {
                    p = 1 + ((lane + r) % 63);
                    q = 1 + ((63 - lane + r) % 63);
                }
                if (p > q) { int t = p; p = q; q = t; }
                float app = sA[p][p], aqq = sA[q][q], apq = sA[p][q];
                bool rot = (apq * apq > eps2 * app * aqq);
                float cc = 1.0f, sn = 0.0f;
                if (rot) {
                    float tau = (aqq - app) / (2.0f * apq);
                    float t = copysignf(1.0f, tau) /
                              (fabsf(tau) + sqrtf(1.0f + tau * tau));
                    cc = rsqrtf(1.0f + t * t);
                    sn = t * cc;
                    sA[p][p] = app - t * apq;
                    sA[q][q] = aqq + t * apq;
                    sA[p][q] = 0.0f;
                }
                spq[lane] = (p << 8) | q;
                scs[lane] = make_float2(cc, sn);
                unsigned msk = __ballot_sync(0xffffffffu, rot);
                if (lane == 0) { sskip = msk; if (msk) sAny = 1; }
            }
            __syncthreads();

            unsigned m = sskip;
            if (m) {
                // --- phase 2a: off-diagonal A blocks (symmetric half) ---
                #pragma unroll
                for (int t = 0; t < 2; t++) {
                    int blk = tid + t * 256;
                    if (blk < 496) {
                        int bb = sblk[blk];
                        int bi = bb >> 8, bj = bb & 255;
                        if (((m >> bi) | (m >> bj)) & 1u) {
                            int pqi = spq[bi], pqj = spq[bj];
                            int pi = pqi >> 8, qi = pqi & 255;
                            int pj = pqj >> 8, qj = pqj & 255;
                            float2 gi = scs[bi], gj = scs[bj];
                            float a  = (pi < pj) ? sA[pi][pj] : sA[pj][pi];
                            float b  = (pi < qj) ? sA[pi][qj] : sA[qj][pi];
                            float c2 = (qi < pj) ? sA[qi][pj] : sA[pj][qi];
                            float d  = (qi < qj) ? sA[qi][qj] : sA[qj][qi];
                            // right (column) rotation G_bj
                            float a1 = gj.x * a  - gj.y * b;
                            float b1 = gj.y * a  + gj.x * b;
                            float c1 = gj.x * c2 - gj.y * d;
                            float d1 = gj.y * c2 + gj.x * d;
                            // left (row) rotation G_bi^T, canonical stores
                            float na = gi.x * a1 - gi.y * c1;
                            float nc = gi.y * a1 + gi.x * c1;
                            float nb = gi.x * b1 - gi.y * d1;
                            float nd = gi.y * b1 + gi.x * d1;
                            if (pi < pj) sA[pi][pj] = na; else sA[pj][pi] = na;
                            if (qi < pj) sA[qi][pj] = nc; else sA[pj][qi] = nc;
                            if (pi < qj) sA[pi][qj] = nb; else sA[qj][pi] = nb;
                            if (qi < qj) sA[qi][qj] = nd; else sA[qj][qi] = nd;
                        }
                    }
                }
                // --- phase 2b: V <- V * G, conflict-free (row varies per lane) ---
                #pragma unroll
                for (int t = 0; t < 8; t++) {
                    int combo = w * 8 + t;           // 0..63
                    int j = combo >> 1;              // pair index (warp-uniform)
                    if ((m >> j) & 1u) {
                        int row = ((combo & 1) << 5) + lane;
                        int pqj = spq[j];
                        int pj = pqj >> 8, qj = pqj & 255;
                        float2 cs = scs[j];
                        float x = sV[row][pj], y = sV[row][qj];
                        sV[row][pj] = cs.x * x - cs.y * y;
                        sV[row][qj] = cs.y * x + cs.x * y;
                    }
                }
            }
            __syncthreads();
        }
        int any = sAny;
        __syncthreads();
        if (!any) break;
    }

    // log of eigenvalues
    if (tid < 64) sl[tid] = logf(fmaxf(sA[tid][tid], 1e-12f));
    __syncthreads();

    // logm = V * diag(log lambda) * V^T, 4x4 register tile per thread
    {
        int i0 = (tid >> 4) << 2;
        int j0 = (tid & 15) << 2;
        float acc[4][4];
        #pragma unroll
        for (int i = 0; i < 4; i++)
            #pragma unroll
            for (int j = 0; j < 4; j++) acc[i][j] = 0.0f;
        for (int k = 0; k < 64; k++) {
            float lk = sl[k];
            float ra0 = sV[i0 + 0][k], ra1 = sV[i0 + 1][k];
            float ra2 = sV[i0 + 2][k], ra3 = sV[i0 + 3][k];
            float rb0 = sV[j0 + 0][k] * lk, rb1 = sV[j0 + 1][k] * lk;
            float rb2 = sV[j0 + 2][k] * lk, rb3 = sV[j0 + 3][k] * lk;
            acc[0][0] += ra0 * rb0; acc[0][1] += ra0 * rb1;
            acc[0][2] += ra0 * rb2; acc[0][3] += ra0 * rb3;
            acc[1][0] += ra1 * rb0; acc[1][1] += ra1 * rb1;
            acc[1][2] += ra1 * rb2; acc[1][3] += ra1 * rb3;
            acc[2][0] += ra2 * rb0; acc[2][1] += ra2 * rb1;
            acc[2][2] += ra2 * rb2; acc[2][3] += ra2 * rb3;
            acc[3][0] += ra3 * rb0; acc[3][1] += ra3 * rb1;
            acc[3][2] += ra3 * rb2; acc[3][3] += ra3 * rb3;
        }
        float* out = dst + (size_t)blockIdx.x * MATSZ;
        #pragma unroll
        for (int i = 0; i < 4; i++) {
            float4 v = make_float4(acc[i][0], acc[i][1], acc[i][2], acc[i][3]);
            *(float4*)(out + (i0 + i) * 64 + j0) = v;
        }
    }
}

// ---------------------------------------------------------------------------
// q[c] = tr(logP_c * A_sym_c) = sum_k logP[c][k] * B[k][c]
// ---------------------------------------------------------------------------
__global__ void compute_q_kernel() {
    int c = blockIdx.x;
    int tid = threadIdx.x;
    __shared__ float sred[256];
    float acc = 0.0f;
    for (int k = tid; k < MATSZ; k += 256)
        acc += g_logP[(size_t)c * MATSZ + k] * g_B[(size_t)k * CDIM + c];
    sred[tid] = acc;
    __syncthreads();
    for (int o = 128; o > 0; o >>= 1) {
        if (tid < o) sred[tid] += sred[tid + o];
        __syncthreads();
    }
    if (tid == 0) g_q[c] = sred[0];
}

// ---------------------------------------------------------------------------
// SGEMM: out[M x 128] = logX[M x 4096] @ B[4096 x 128] - q[c]
// BM=64, BN=128, BK=16, TM=TN=8, 128 threads.
// ---------------------------------------------------------------------------
#define BM 64
#define BN 128
#define BK 16
__global__ __launch_bounds__(128) void gemm_kernel(
    const float* __restrict__ Amat, float* __restrict__ out) {
    __shared__ float As[BK][BM];   // transposed A tile
    __shared__ float Bs[BK][BN];
    __shared__ float sqv[BN];

    int tid = threadIdx.x;
    int rowg = tid >> 4;    // 0..7
    int colg = tid & 15;    // 0..15
    size_t row0 = (size_t)blockIdx.x * BM;

    if (tid < BN) sqv[tid] = g_q[tid];

    float acc[8][8];
    #pragma unroll
    for (int i = 0; i < 8; i++)
        #pragma unroll
        for (int j = 0; j < 8; j++) acc[i][j] = 0.0f;

    for (int kt = 0; kt < MATSZ; kt += BK) {
        #pragma unroll
        for (int l = 0; l < 2; l++) {
            int lin = tid + l * 128;
            int r = lin >> 2;
            int k4 = (lin & 3) * 4;
            float4 v = *(const float4*)(Amat + (row0 + r) * MATSZ + kt + k4);
            As[k4 + 0][r] = v.x; As[k4 + 1][r] = v.y;
            As[k4 + 2][r] = v.z; As[k4 + 3][r] = v.w;
        }
        #pragma unroll
        for (int l = 0; l < 4; l++) {
            int lin = tid + l * 128;
            int r = lin >> 5;
            int c4 = (lin & 31) * 4;
            *(float4*)&Bs[r][c4] =
                *(const float4*)(g_B + (size_t)(kt + r) * CDIM + c4);
        }
        __syncthreads();
        #pragma unroll
        for (int k = 0; k < BK; k++) {
            float ra[8], rb[8];
            #pragma unroll
            for (int i = 0; i < 8; i++) ra[i] = As[k][rowg * 8 + i];
            #pragma unroll
            for (int j = 0; j < 8; j++) rb[j] = Bs[k][colg * 8 + j];
            #pragma unroll
            for (int i = 0; i < 8; i++)
                #pragma unroll
                for (int j = 0; j < 8; j++)
                    acc[i][j] += ra[i] * rb[j];
        }
        __syncthreads();
    }
    #pragma unroll
    for (int i = 0; i < 8; i++) {
        size_t rr = row0 + rowg * 8 + i;
        #pragma unroll
        for (int j = 0; j < 8; j++) {
            int cc = colg * 8 + j;
            out[rr * CDIM + cc] = acc[i][j] - sqv[cc];
        }
    }
}

// ---------------------------------------------------------------------------
extern "C" void kernel_launch(void* const* d_in, const int* in_sizes, int n_in,
                              void* d_out, int out_size) {
    const float* X = (const float*)d_in[0];   // (32768, 64, 64)
    const float* P = (const float*)d_in[1];   // (128, 64, 64)
    const float* A = (const float*)d_in[2];   // (128, 64, 64)
    float* out = (float*)d_out;               // (32768, 128)

    float *p_logX, *p_logP;
    cudaGetSymbolAddress((void**)&p_logX, g_logX);
    cudaGetSymbolAddress((void**)&p_logP, g_logP);

    prep_b_kernel<<<(MATSZ * CDIM) / 256, 256>>>(A);
    jacobi_logm_kernel<<<CDIM, 256>>>(P, p_logP);
    compute_q_kernel<<<CDIM, 256>>>();
    jacobi_logm_kernel<<<NMAT, 256>>>(X, p_logX);
    gemm_kernel<<<NMAT / BM, 128>>>(p_logX, out);
}